// round 7
// baseline (speedup 1.0000x reference)
#include <cuda_runtime.h>
#include <cstdint>

#define SEQ 2048
#define NB 64
#define NF 16
#define HD 512
#define ROWB 2048                        // bytes per hidden row
#define SLOT_PAD 516                     // 129 16B-units/row: ≡1 mod 8 -> conflict-free
#define SLOT_BYTES (NF * SLOT_PAD * 4)   // 33024
#define G_TOK 8                          // tokens per group (warp-owned, full d)
#define STG_ROW 528                      // staged row stride (512 + 16: 33 units, ≡1 mod 8)
#define STAGE_B (G_TOK * STG_ROW)        // 4224
#define NW 8                             // warps per block
#define RING_BYTES (NW * 2 * STAGE_B)    // 67584
#define MBAR_OFF (SLOT_BYTES + RING_BYTES)          // 100608
#define SMEM_TOTAL (MBAR_OFF + NW * 2 * 8)          // 100736 -> 2 blocks/SM
#define GRID_X 296
#define TOTAL_WARPS (GRID_X * NW)        // 2368 = 37*64: each warp has a fixed batch
#define GX_STRIDE 37                     // group-x stride per warp

// Scratch (allocation-free rule: __device__ globals)
__device__ int g_list[NB * SEQ];   // packed: token_pos | (seg << 16), compacted per batch
__device__ int g_cnt[NB];

__device__ __forceinline__ unsigned long long ffma2(unsigned long long a,
                                                    unsigned long long b,
                                                    unsigned long long c) {
    unsigned long long d;
    asm("fma.rn.f32x2 %0, %1, %2, %3;" : "=l"(d) : "l"(a), "l"(b), "l"(c));
    return d;
}

__device__ __forceinline__ void mbar_init(unsigned mbar, unsigned count) {
    asm volatile("mbarrier.init.shared.b64 [%0], %1;" :: "r"(mbar), "r"(count) : "memory");
}
__device__ __forceinline__ void mbar_expect_tx(unsigned mbar, unsigned bytes) {
    asm volatile("mbarrier.arrive.expect_tx.shared.b64 _, [%0], %1;"
                 :: "r"(mbar), "r"(bytes) : "memory");
}
__device__ __forceinline__ void mbar_wait(unsigned mbar, unsigned parity) {
    unsigned done;
    asm volatile(
        "{\n\t.reg .pred p;\n\t"
        "mbarrier.try_wait.parity.acquire.cta.shared::cta.b64 p, [%1], %2;\n\t"
        "selp.b32 %0, 1, 0, p;\n\t}"
        : "=r"(done) : "r"(mbar), "r"(parity) : "memory");
    while (!done) {
        asm volatile(
            "{\n\t.reg .pred p;\n\t"
            "mbarrier.try_wait.parity.acquire.cta.shared::cta.b64 p, [%1], %2, 0x989680;\n\t"
            "selp.b32 %0, 1, 0, p;\n\t}"
            : "=r"(done) : "r"(mbar), "r"(parity) : "memory");
    }
}
__device__ __forceinline__ void bulk_cp(unsigned dst_smem, const void* src, unsigned mbar) {
    asm volatile(
        "cp.async.bulk.shared::cta.global.mbarrier::complete_tx::bytes [%0], [%1], %2, [%3];"
        :: "r"(dst_smem), "l"(src), "r"(512u), "r"(mbar) : "memory");
}
__device__ __forceinline__ void fence_async_shared() {
    asm volatile("fence.proxy.async.shared::cta;" ::: "memory");
}

// ---------------------------------------------------------------------------
// Block-wide exclusive scan over 256 threads
// ---------------------------------------------------------------------------
__device__ __forceinline__ int block_exscan(int v, int* sh) {
    int lane = threadIdx.x & 31;
    int w = threadIdx.x >> 5;
    int incl = v;
#pragma unroll
    for (int o = 1; o < 32; o <<= 1) {
        int n = __shfl_up_sync(0xFFFFFFFFu, incl, o);
        if (lane >= o) incl += n;
    }
    if (lane == 31) sh[w] = incl;
    __syncthreads();
    if (threadIdx.x < 8) {
        int x = sh[threadIdx.x];
#pragma unroll
        for (int o = 1; o < 8; o <<= 1) {
            int n = __shfl_up_sync(0xFFu, x, o);
            if (threadIdx.x >= (unsigned)o) x += n;
        }
        sh[threadIdx.x] = x;
    }
    __syncthreads();
    int wofs = (w == 0) ? 0 : sh[w - 1];
    return wofs + incl - v;
}

// ---------------------------------------------------------------------------
// Kernel 1 (fused): zero output (all 256 blocks) + per-batch span ids +
// compaction (first 64 blocks).
// ---------------------------------------------------------------------------
__global__ __launch_bounds__(256) void seg_zero_kernel(const int* __restrict__ labels,
                                                       const int* pB, const int* pI,
                                                       const int* pMS,
                                                       float* __restrict__ out,
                                                       int out_n) {
    {
        int tid = blockIdx.x * 256 + threadIdx.x;
        int nthreads = gridDim.x * 256;
        int n4 = out_n >> 2;
        float4 z = make_float4(0.f, 0.f, 0.f, 0.f);
        for (int i = tid; i < n4; i += nthreads)
            reinterpret_cast<float4*>(out)[i] = z;
        for (int i = (n4 << 2) + tid; i < out_n; i += nthreads)
            out[i] = 0.0f;
    }
    if (blockIdx.x >= NB) return;

    __shared__ int sh[8];
    int b = blockIdx.x;
    int t = threadIdx.x;
    int Bv = pB ? *pB : 1;
    int Iv = pI ? *pI : 2;
    int MS = pMS ? *pMS : 512;

    const int4* row = reinterpret_cast<const int4*>(labels + b * SEQ) + t * 2;
    int4 a = row[0];
    int4 c = row[1];
    int lab[8] = {a.x, a.y, a.z, a.w, c.x, c.y, c.z, c.w};

    int incl[8];
    int csum = 0;
#pragma unroll
    for (int i = 0; i < 8; i++) {
        csum += (lab[i] == Bv);
        incl[i] = csum;
    }
    int ex = block_exscan(csum, sh);

    int seg[8], vfl[8];
    int vtot = 0;
#pragma unroll
    for (int i = 0; i < 8; i++) {
        seg[i] = ex + incl[i] - 1;
        vfl[i] = ((lab[i] == Bv) || (lab[i] == Iv)) && seg[i] >= 0 && seg[i] < MS;
        vtot += vfl[i];
    }
    __syncthreads();
    int vex = block_exscan(vtot, sh);

    int pos = vex;
#pragma unroll
    for (int i = 0; i < 8; i++) {
        if (vfl[i]) {
            g_list[b * SEQ + pos] = (t * 8 + i) | (seg[i] << 16);
            pos++;
        }
    }
    if (t == 255) g_cnt[b] = vex + vtot;
}

// ---------------------------------------------------------------------------
// Kernel 2: TMA-bulk gather-projection, warp-autonomous.
//
// Warp wg = blockIdx.x*8+w owns batch b = wg&63 and groups gx = (wg>>6)+37k
// (contiguous working k's). Group = 8 compacted tokens x full 512 d, streamed
// as 4 stages of 128 d: 8 x cp.async.bulk (512 B each, gmem-contiguous) into
// a 528B-strided smem buffer (stride 33 units ≡1 mod 8: conflict-free), via
// a 2-deep mbarrier ring with issue-ahead 2.
//
// Compute: lane (tp = l>>3, fh = l&7) tiles tokens {tp, tp+4} x f={fh,fh+8};
// per 16B chunk: 2 H + 2 S LDS.128 (broadcast/conflict-free) -> 8 FFMA2.
// Full-d sums: one atomicAdd per (token, f) at group end.
// ---------------------------------------------------------------------------
__global__ __launch_bounds__(256, 2) void proj_kernel(const float* __restrict__ hidden,
                                                      const float* __restrict__ slot,
                                                      const int* pMS,
                                                      float* __restrict__ out) {
    extern __shared__ float smem[];
    float* slot_sh = smem;
    int MS = pMS ? *pMS : 512;

    unsigned smem_base;
    {
        unsigned long long tmp = __cvta_generic_to_shared(smem);
        smem_base = (unsigned)tmp;
    }

    // init mbarriers (16 per block)
    if (threadIdx.x < NW * 2)
        mbar_init(smem_base + MBAR_OFF + threadIdx.x * 8, 1);

    // stage slot_embs transposed: slot_sh[f][d]
    for (int i = threadIdx.x; i < HD * NF; i += 256) {
        int d = i >> 4;
        int f = i & 15;
        slot_sh[f * SLOT_PAD + d] = slot[i];
    }
    __syncthreads();

    int w = threadIdx.x >> 5;
    int lane = threadIdx.x & 31;
    int tp = lane >> 3;       // token pair id (0..3): owns tokens {tp, tp+4}
    int fh = lane & 7;        // f half

    int wg = blockIdx.x * NW + w;
    int b = wg & 63;
    int gx0 = wg >> 6;        // 0..36
    int cnt = g_cnt[b];
    int limit = (cnt + G_TOK - 1) >> 3;    // number of working gx values
    int ngroups = (gx0 < limit) ? ((limit - 1 - gx0) / GX_STRIDE + 1) : 0;
    if (ngroups == 0) return;
    int nstages = ngroups * 4;

    unsigned ring0 = smem_base + SLOT_BYTES + w * 2 * STAGE_B;
    unsigned mbar0 = smem_base + MBAR_OFF + w * 2 * 8;
    const char* hb = reinterpret_cast<const char*>(hidden) + (size_t)b * SEQ * ROWB;
    const int* lst = g_list + b * SEQ;

    // row byte-offset for token (lane&7) of group k
    auto load_rofs = [&](int k) -> unsigned {
        int ti = (gx0 + GX_STRIDE * k) * G_TOK + (lane & 7);
        if (ti >= cnt) ti = cnt - 1;
        return (unsigned)(lst[ti] & 0xFFFF) * ROWB;
    };

    // issue stage i (s = i&3 of group i>>2) using current rofs
    auto issue = [&](int i, unsigned rofs) {
        unsigned buf = ring0 + (i & 1) * STAGE_B;
        unsigned mbar = mbar0 + (i & 1) * 8;
        if (lane == 0) mbar_expect_tx(mbar, G_TOK * 512u);
        __syncwarp();
        if (lane < G_TOK)
            bulk_cp(buf + lane * STG_ROW, hb + rofs + (i & 3) * 512, mbar);
    };

    unsigned long long a00, a01, a10, a11;

    auto comp = [&](int i) {
        const char* buf;
        {
            unsigned long long gp;
            asm("cvta.shared.u64 %0, %1;" : "=l"(gp)
                : "l"((unsigned long long)(ring0 + (i & 1) * STAGE_B)));
            buf = reinterpret_cast<const char*>(gp);
        }
        int s = i & 3;
        const float* s0 = slot_sh + fh * SLOT_PAD + s * 128;
        const float* s1 = s0 + 8 * SLOT_PAD;
        const char* h0 = buf + tp * STG_ROW;
        const char* h1 = buf + (tp + 4) * STG_ROW;
#pragma unroll
        for (int c = 0; c < 32; c++) {
            ulonglong2 S0 = *reinterpret_cast<const ulonglong2*>(s0 + c * 4);
            ulonglong2 S1 = *reinterpret_cast<const ulonglong2*>(s1 + c * 4);
            ulonglong2 H0 = *reinterpret_cast<const ulonglong2*>(h0 + c * 16);
            ulonglong2 H1 = *reinterpret_cast<const ulonglong2*>(h1 + c * 16);
            a00 = ffma2(H0.x, S0.x, a00);
            a00 = ffma2(H0.y, S0.y, a00);
            a01 = ffma2(H0.x, S1.x, a01);
            a01 = ffma2(H0.y, S1.y, a01);
            a10 = ffma2(H1.x, S0.x, a10);
            a10 = ffma2(H1.y, S0.y, a10);
            a11 = ffma2(H1.x, S1.x, a11);
            a11 = ffma2(H1.y, S1.y, a11);
        }
    };

    unsigned rofs = load_rofs(0);
    issue(0, rofs);
    if (nstages > 1) issue(1, rofs);

    for (int i = 0; i < nstages; i++) {
        mbar_wait(mbar0 + (i & 1) * 8, (i >> 1) & 1);
        if ((i & 3) == 0) { a00 = a01 = a10 = a11 = 0ull; }
        comp(i);
        if ((i & 3) == 3) {
            // scatter full-d sums for group i>>2
            int gx = gx0 + GX_STRIDE * (i >> 2);
#pragma unroll
            for (int j = 0; j < 2; j++) {
                int ti = gx * G_TOK + tp + 4 * j;
                if (ti < cnt) {
                    int p = lst[ti];
                    float* op = out + ((size_t)b * MS + (p >> 16)) * NF;
                    unsigned long long vx = j ? a10 : a00;
                    unsigned long long vy = j ? a11 : a01;
                    float2 v0 = *reinterpret_cast<float2*>(&vx);
                    float2 v1 = *reinterpret_cast<float2*>(&vy);
                    atomicAdd(op + fh, v0.x + v0.y);
                    atomicAdd(op + fh + 8, v1.x + v1.y);
                }
            }
        }
        fence_async_shared();   // order LDS reads before refilling this buffer
        int nx = i + 2;
        if (nx < nstages) {
            if ((nx & 3) == 0) rofs = load_rofs(nx >> 2);
            issue(nx, rofs);
        }
    }
}

// ---------------------------------------------------------------------------
extern "C" void kernel_launch(void* const* d_in, const int* in_sizes, int n_in,
                              void* d_out, int out_size) {
    const float* hidden = (const float*)d_in[0];
    const float* slot = (const float*)d_in[1];
    const int* labels = (const int*)d_in[2];
    const int* pB = (n_in > 3) ? (const int*)d_in[3] : nullptr;
    const int* pI = (n_in > 4) ? (const int*)d_in[4] : nullptr;
    const int* pMS = (n_in > 5) ? (const int*)d_in[5] : nullptr;
    float* out = (float*)d_out;

    static bool attr_set = false;
    if (!attr_set) {
        cudaFuncSetAttribute(proj_kernel, cudaFuncAttributeMaxDynamicSharedMemorySize,
                             SMEM_TOTAL);
        attr_set = true;
    }

    seg_zero_kernel<<<256, 256>>>(labels, pB, pI, pMS, out, out_size);
    proj_kernel<<<GRID_X, 256, SMEM_TOTAL>>>(hidden, slot, pMS, out);
}

// round 8
// speedup vs baseline: 1.4646x; 1.4646x over previous
#include <cuda_runtime.h>
#include <cstdint>

#define SEQ 2048
#define NB 64
#define NF 16
#define HD 512
#define ROWB 2048                        // bytes per hidden row
#define SLOT_PAD 516                     // 129 16B-units/row: ≡1 mod 8 -> conflict-free
#define SLOT_BYTES (NF * SLOT_PAD * 4)   // 33024
#define U_TOK 32                         // tokens per unit (block)
#define W_TOK 16                         // tokens per warp
#define STAGE_B 2048                     // 16 tok x 32 d x 4B
#define RING_STAGES 4
#define NW 8                             // warps/block: 4 d-quarters x 2 token-halves
#define SMEM_CNT_OFF (SLOT_BYTES + NW * RING_STAGES * STAGE_B)   // 98560
#define SMEM_TOTAL (SMEM_CNT_OFF + NB * 4)                       // 98816 -> 2 blocks/SM
#define N_UNITS ((SEQ / U_TOK) * NB)     // 4096, x-major: u = x*64 + b
#define GRID_X 296                       // 2/SM x 148 SM

// Scratch (allocation-free rule: __device__ globals)
__device__ int g_list[NB * SEQ];   // packed: token_pos | (seg << 16), compacted per batch
__device__ int g_cnt[NB];

__device__ __forceinline__ unsigned long long ffma2(unsigned long long a,
                                                    unsigned long long b,
                                                    unsigned long long c) {
    unsigned long long d;
    asm("fma.rn.f32x2 %0, %1, %2, %3;" : "=l"(d) : "l"(a), "l"(b), "l"(c));
    return d;
}

__device__ __forceinline__ void cp16(void* dst_smem, const void* src) {
    unsigned saddr = (unsigned)__cvta_generic_to_shared(dst_smem);
    asm volatile("cp.async.cg.shared.global [%0], [%1], 16;" :: "r"(saddr), "l"(src));
}
__device__ __forceinline__ void cp_commit() {
    asm volatile("cp.async.commit_group;");
}
template <int N>
__device__ __forceinline__ void cp_wait() {
    asm volatile("cp.async.wait_group %0;" :: "n"(N));
}

// stage smem swizzle: 16B-unit address for (token t in 0..15, chunk c in 0..7).
// Reads (fixed c, t = {j, j+4, j+8, j+12}) hit 4 DISTINCT bank-quads:
// bank = (c + t + (t>>3)) & 7 -> j, j+4, j+1, j+5 (all distinct).
// Stores (one instr: t spans 8 values at fixed t>>3, c spans 4) cover each
// bank exactly 4x -> minimal 4 wavefronts.
__device__ __forceinline__ int sw16(int t, int c) {
    return t * 8 + ((c + t + (t >> 3)) & 7);
}

// ---------------------------------------------------------------------------
// Block-wide exclusive scan over 256 threads
// ---------------------------------------------------------------------------
__device__ __forceinline__ int block_exscan(int v, int* sh) {
    int lane = threadIdx.x & 31;
    int w = threadIdx.x >> 5;
    int incl = v;
#pragma unroll
    for (int o = 1; o < 32; o <<= 1) {
        int n = __shfl_up_sync(0xFFFFFFFFu, incl, o);
        if (lane >= o) incl += n;
    }
    if (lane == 31) sh[w] = incl;
    __syncthreads();
    if (threadIdx.x < 8) {
        int x = sh[threadIdx.x];
#pragma unroll
        for (int o = 1; o < 8; o <<= 1) {
            int n = __shfl_up_sync(0xFFu, x, o);
            if (threadIdx.x >= (unsigned)o) x += n;
        }
        sh[threadIdx.x] = x;
    }
    __syncthreads();
    int wofs = (w == 0) ? 0 : sh[w - 1];
    return wofs + incl - v;
}

// ---------------------------------------------------------------------------
// Kernel 1 (fused): zero output (all 256 blocks) + per-batch span ids +
// compaction (first 64 blocks).
// ---------------------------------------------------------------------------
__global__ __launch_bounds__(256) void seg_zero_kernel(const int* __restrict__ labels,
                                                       const int* pB, const int* pI,
                                                       const int* pMS,
                                                       float* __restrict__ out,
                                                       int out_n) {
    {
        int tid = blockIdx.x * 256 + threadIdx.x;
        int nthreads = gridDim.x * 256;
        int n4 = out_n >> 2;
        float4 z = make_float4(0.f, 0.f, 0.f, 0.f);
        for (int i = tid; i < n4; i += nthreads)
            reinterpret_cast<float4*>(out)[i] = z;
        for (int i = (n4 << 2) + tid; i < out_n; i += nthreads)
            out[i] = 0.0f;
    }
    if (blockIdx.x >= NB) return;

    __shared__ int sh[8];
    int b = blockIdx.x;
    int t = threadIdx.x;
    int Bv = pB ? *pB : 1;
    int Iv = pI ? *pI : 2;
    int MS = pMS ? *pMS : 512;

    const int4* row = reinterpret_cast<const int4*>(labels + b * SEQ) + t * 2;
    int4 a = row[0];
    int4 c = row[1];
    int lab[8] = {a.x, a.y, a.z, a.w, c.x, c.y, c.z, c.w};

    int incl[8];
    int csum = 0;
#pragma unroll
    for (int i = 0; i < 8; i++) {
        csum += (lab[i] == Bv);
        incl[i] = csum;
    }
    int ex = block_exscan(csum, sh);

    int seg[8], vfl[8];
    int vtot = 0;
#pragma unroll
    for (int i = 0; i < 8; i++) {
        seg[i] = ex + incl[i] - 1;
        vfl[i] = ((lab[i] == Bv) || (lab[i] == Iv)) && seg[i] >= 0 && seg[i] < MS;
        vtot += vfl[i];
    }
    __syncthreads();
    int vex = block_exscan(vtot, sh);

    int pos = vex;
#pragma unroll
    for (int i = 0; i < 8; i++) {
        if (vfl[i]) {
            g_list[b * SEQ + pos] = (t * 8 + i) | (seg[i] << 16);
            pos++;
        }
    }
    if (t == 255) g_cnt[b] = vex + vtot;
}

// ---------------------------------------------------------------------------
// Kernel 2: warp-autonomous gather-projection with FLAT 4-deep pipeline.
//
// Unit = 32 compacted tokens of batch b (u = x*64 + b, x-major). Block's
// units: u = bid + k*GRID_X. Warp (q = w&3, h = w>>2) owns d-quarter q of
// tokens [16h, 16h+16) of each unit. Each unit = 4 stages of 32 d.
//
// The stage stream is CONTINUOUS across units: issue cursor runs 3 stages
// ahead of the compute cursor through a private 4-slot ring (8 KB/warp), so
// the pipeline never drains until the warp's whole work list ends.
//
// Staging: lane (r4, qq) covers tokens {r4, r4+8}, chunks {qq, qq+4}:
// 4 cp16/lane/stage (each instr: 8 rows x 64B coalesced).
// Compute: lane (tg, fh) tiles 4 tokens x f={fh, fh+8}: per 16B chunk
// 2 S + 4 H LDS.128 (conflict-free under sw16) -> 16 FFMA2. acc = 16 regs.
// ---------------------------------------------------------------------------
__global__ __launch_bounds__(256, 2) void proj_kernel(const float* __restrict__ hidden,
                                                      const float* __restrict__ slot,
                                                      const int* pMS,
                                                      float* __restrict__ out) {
    extern __shared__ float smem[];
    float* slot_sh = smem;
    char* ringbase = reinterpret_cast<char*>(smem) + SLOT_BYTES;
    int* cnts = reinterpret_cast<int*>(reinterpret_cast<char*>(smem) + SMEM_CNT_OFF);
    int MS = pMS ? *pMS : 512;

    // stage slot_embs transposed: slot_sh[f][d]; cache per-batch counts
    for (int i = threadIdx.x; i < HD * NF; i += 256) {
        int d = i >> 4;
        int f = i & 15;
        slot_sh[f * SLOT_PAD + d] = slot[i];
    }
    if (threadIdx.x < NB) cnts[threadIdx.x] = g_cnt[threadIdx.x];
    __syncthreads();

    int w = threadIdx.x >> 5;
    int lane = threadIdx.x & 31;
    int q = w & 3;            // d-quarter
    int h = w >> 2;           // token half
    int r4 = lane >> 2;       // staging token group (0..7)
    int qq = lane & 3;        // staging chunk quad (0..3)
    int tg = lane >> 3;       // compute token group (0..3)
    int fh = lane & 7;        // compute f half (0..7)
    char* ring0 = ringbase + w * RING_STAGES * STAGE_B;

    int dst16[2][2];
#pragma unroll
    for (int m = 0; m < 2; m++) {
        dst16[m][0] = sw16(r4 + 8 * m, qq) * 16;
        dst16[m][1] = sw16(r4 + 8 * m, qq + 4) * 16;
    }

    const char* hbase = reinterpret_cast<const char*>(hidden) + q * 512;

    // total stages for this block's warp (uniform across warps of the block)
    int total = 0;
    for (int u = blockIdx.x; u < N_UNITS; u += GRID_X)
        if ((u >> 6) * U_TOK < cnts[u & 63]) total++;
    if (total == 0) return;
    total *= 4;

    // ---- issue cursor ----
    int u_i = blockIdx.x;
    while ((u_i >> 6) * U_TOK >= cnts[u_i & 63]) u_i += GRID_X;
    unsigned ofs_i[2];
    int s_i = 0;    // stage within issue unit
    int isl = 0;    // stages issued

    auto load_ofs = [&](int u) {
        int x = u >> 6;
        int b = u & 63;
        int cnt = cnts[b];
        int t0 = x * U_TOK + h * W_TOK;
#pragma unroll
        for (int m = 0; m < 2; m++) {
            int ti = t0 + r4 + 8 * m;
            if (ti >= cnt) ti = cnt - 1;
            ofs_i[m] = ((unsigned)b * SEQ + (unsigned)(g_list[b * SEQ + ti] & 0xFFFF)) * ROWB;
        }
    };
    load_ofs(u_i);

    auto issue_one = [&]() {
        char* buf = ring0 + (isl & 3) * STAGE_B;
#pragma unroll
        for (int m = 0; m < 2; m++) {
            const char* src = hbase + ofs_i[m] + s_i * 128;
            cp16(buf + dst16[m][0], src + qq * 16);
            cp16(buf + dst16[m][1], src + (qq + 4) * 16);
        }
        cp_commit();
        isl++;
        if (++s_i == 4) {
            s_i = 0;
            do {
                u_i += GRID_X;
            } while (u_i < N_UNITS && (u_i >> 6) * U_TOK >= cnts[u_i & 63]);
            if (u_i < N_UNITS) load_ofs(u_i);
        }
    };

    int pre = total < 3 ? total : 3;
    for (int k = 0; k < pre; k++) issue_one();

    // ---- compute cursor ----
    int u_c = blockIdx.x;
    while ((u_c >> 6) * U_TOK >= cnts[u_c & 63]) u_c += GRID_X;

    unsigned long long acc[4][2];

    for (int i = 0; i < total; i++) {
        int ahead = total - 1 - i;
        if (ahead >= 2) cp_wait<2>();
        else if (ahead == 1) cp_wait<1>();
        else cp_wait<0>();
        __syncwarp();

        int s = i & 3;   // stage-in-unit (units are 4-stage aligned)
        if (s == 0) {
#pragma unroll
            for (int j = 0; j < 4; j++) {
                acc[j][0] = 0ull;
                acc[j][1] = 0ull;
            }
        }

        const char* buf = ring0 + (i & 3) * STAGE_B;
        const float* s0p = slot_sh + fh * SLOT_PAD + q * 128 + s * 32;
        const float* s1p = s0p + 8 * SLOT_PAD;
#pragma unroll
        for (int c = 0; c < 8; c++) {
            ulonglong2 S0 = *reinterpret_cast<const ulonglong2*>(s0p + c * 4);
            ulonglong2 S1 = *reinterpret_cast<const ulonglong2*>(s1p + c * 4);
#pragma unroll
            for (int j = 0; j < 4; j++) {
                int t = 4 * tg + j;
                ulonglong2 H = *reinterpret_cast<const ulonglong2*>(buf + sw16(t, c) * 16);
                acc[j][0] = ffma2(H.x, S0.x, acc[j][0]);
                acc[j][0] = ffma2(H.y, S0.y, acc[j][0]);
                acc[j][1] = ffma2(H.x, S1.x, acc[j][1]);
                acc[j][1] = ffma2(H.y, S1.y, acc[j][1]);
            }
        }

        if (s == 3) {
            // scatter quarter-d sums for unit u_c, then advance
            int x = u_c >> 6;
            int b = u_c & 63;
            int cnt = cnts[b];
            int t0 = x * U_TOK + h * W_TOK;
            const int* lst = g_list + b * SEQ;
#pragma unroll
            for (int j = 0; j < 4; j++) {
                int ti = t0 + 4 * tg + j;
                if (ti < cnt) {
                    int p = lst[ti];
                    float* op = out + ((size_t)b * MS + (p >> 16)) * NF;
                    float2 v0 = *reinterpret_cast<float2*>(&acc[j][0]);
                    float2 v1 = *reinterpret_cast<float2*>(&acc[j][1]);
                    atomicAdd(op + fh, v0.x + v0.y);
                    atomicAdd(op + fh + 8, v1.x + v1.y);
                }
            }
            do {
                u_c += GRID_X;
            } while (u_c < N_UNITS && (u_c >> 6) * U_TOK >= cnts[u_c & 63]);
        }

        __syncwarp();   // all lanes done reading ring slot before it is refilled
        if (isl < total) issue_one();
    }
}

// ---------------------------------------------------------------------------
extern "C" void kernel_launch(void* const* d_in, const int* in_sizes, int n_in,
                              void* d_out, int out_size) {
    const float* hidden = (const float*)d_in[0];
    const float* slot = (const float*)d_in[1];
    const int* labels = (const int*)d_in[2];
    const int* pB = (n_in > 3) ? (const int*)d_in[3] : nullptr;
    const int* pI = (n_in > 4) ? (const int*)d_in[4] : nullptr;
    const int* pMS = (n_in > 5) ? (const int*)d_in[5] : nullptr;
    float* out = (float*)d_out;

    static bool attr_set = false;
    if (!attr_set) {
        cudaFuncSetAttribute(proj_kernel, cudaFuncAttributeMaxDynamicSharedMemorySize,
                             SMEM_TOTAL);
        attr_set = true;
    }

    seg_zero_kernel<<<256, 256>>>(labels, pB, pI, pMS, out, out_size);
    proj_kernel<<<GRID_X, 256, SMEM_TOTAL>>>(hidden, slot, pMS, out);
}